// round 16
// baseline (speedup 1.0000x reference)
#include <cuda_runtime.h>
#include <cuda_fp16.h>
#include <cstdint>

// Problem constants (fixed by setup_inputs)
#define T_TOK   8192      // B*S = 4*2048
#define D_IN    2048
#define D_OUT   2048
#define R_RANK  64
#define N_EXP   16
#define N_COLS  80        // R + E combined small-GEMM width
#define N_PAIR  256       // expert-pair bins (lo*16+hi, lo<hi populated)

// ---------------- device scratch (no allocations allowed) ----------------
__device__ float  g_S[T_TOK * N_COLS];        // [token][0..63]=res_hidden, [64..79]=router logits
__device__ int    g_pcnt[N_PAIR];             // per-pair token counts
__device__ int    g_ptok[N_PAIR * T_TOK / 4]; // pair token ids (cap 2048/bin)
__device__ float2 g_pw [N_PAIR * T_TOK / 4];  // (w_lo, w_hi) per slot
// fp16 copies for the tensor-core GEMMs
__device__ __half g_xh[T_TOK * D_IN];
__device__ __half g_wh[D_OUT * D_IN];
__device__ __half g_bh[N_EXP * D_OUT * R_RANK];

#define PAIR_CAP (T_TOK / 4)   // 2048 slots per bin

// ---------------- helpers ----------------
__device__ __forceinline__ uint32_t smem_u32(const void* p) {
    uint32_t a;
    asm("{ .reg .u64 t; cvta.to.shared.u64 t, %1; cvt.u32.u64 %0, t; }" : "=r"(a) : "l"(p));
    return a;
}
__device__ __forceinline__ void cp16(uint32_t s, const void* g) {
    asm volatile("cp.async.cg.shared.global [%0], [%1], 16;" :: "r"(s), "l"(g) : "memory");
}
__device__ __forceinline__ void ldmatrix_x4(uint32_t* r, uint32_t addr) {
    asm volatile("ldmatrix.sync.aligned.m8n8.x4.shared.b16 {%0,%1,%2,%3}, [%4];"
                 : "=r"(r[0]), "=r"(r[1]), "=r"(r[2]), "=r"(r[3]) : "r"(addr));
}
__device__ __forceinline__ void mma16816h(float* c, const uint32_t* a, uint32_t b0, uint32_t b1) {
    asm volatile(
        "mma.sync.aligned.m16n8k16.row.col.f32.f16.f16.f32 "
        "{%0,%1,%2,%3}, {%4,%5,%6,%7}, {%8,%9}, {%0,%1,%2,%3};"
        : "+f"(c[0]), "+f"(c[1]), "+f"(c[2]), "+f"(c[3])
        : "r"(a[0]), "r"(a[1]), "r"(a[2]), "r"(a[3]), "r"(b0), "r"(b1));
}
__device__ __forceinline__ void red_v2(float* p, float x, float y) {
    asm volatile("red.global.add.v2.f32 [%0], {%1,%2};"
                 :: "l"(p), "f"(x), "f"(y) : "memory");
}
#define CP_COMMIT() asm volatile("cp.async.commit_group;" ::: "memory")
#define CP_WAIT(n)  asm volatile("cp.async.wait_group %0;" :: "n"(n) : "memory")

// ============================================================================
// Kernel 0: fp32 -> fp16
// ============================================================================
__global__ __launch_bounds__(256) void k0_cvt(
    const float* __restrict__ src, __half* __restrict__ dst, int n4)
{
    int i = blockIdx.x * blockDim.x + threadIdx.x;
    if (i >= n4) return;
    float4 v = *(const float4*)&src[(size_t)i * 4];
    __half h[4];
    h[0] = __float2half_rn(v.x); h[1] = __float2half_rn(v.y);
    h[2] = __float2half_rn(v.z); h[3] = __float2half_rn(v.w);
    *(uint2*)&dst[(size_t)i * 4] = *(uint2*)h;
}

// ============================================================================
// Kernel 1: S = x @ [A^T | W_router^T]  (fp32 SIMT) + fused top-2 pair router
// ============================================================================
__global__ __launch_bounds__(256) void k1_small_gemm(
    const float* __restrict__ x,
    const float* __restrict__ A,
    const float* __restrict__ Wr)
{
    __shared__ float xs[128][68];
    __shared__ float ws[40][68];

    const int tid = threadIdx.x;
    const int m0 = blockIdx.y * 128;
    const int c0 = blockIdx.x * 40;
    const int tg = tid >> 3;
    const int cg = tid & 7;

    float acc[4][5];
#pragma unroll
    for (int i = 0; i < 4; i++)
#pragma unroll
        for (int j = 0; j < 5; j++) acc[i][j] = 0.f;

    for (int k0 = 0; k0 < D_IN; k0 += 64) {
#pragma unroll
        for (int it = 0; it < 8; it++) {
            int q = tid + it * 256;
            int row = q >> 4;
            int kc = (q & 15) << 2;
            float4 v = *(const float4*)&x[(size_t)(m0 + row) * D_IN + k0 + kc];
            *(float4*)&xs[row][kc] = v;
        }
        for (int q = tid; q < 40 * 16; q += 256) {
            int col = q >> 4;
            int kc = (q & 15) << 2;
            int gc = c0 + col;
            const float* src = (gc < R_RANK) ? (A + (size_t)gc * D_IN)
                                             : (Wr + (size_t)(gc - R_RANK) * D_IN);
            float4 v = *(const float4*)&src[k0 + kc];
            *(float4*)&ws[col][kc] = v;
        }
        __syncthreads();

#pragma unroll 16
        for (int kk = 0; kk < 64; kk++) {
            float av[4], bv[5];
#pragma unroll
            for (int i = 0; i < 4; i++) av[i] = xs[tg * 4 + i][kk];
#pragma unroll
            for (int j = 0; j < 5; j++) bv[j] = ws[cg * 5 + j][kk];
#pragma unroll
            for (int i = 0; i < 4; i++)
#pragma unroll
                for (int j = 0; j < 5; j++) acc[i][j] += av[i] * bv[j];
        }
        __syncthreads();
    }

#pragma unroll
    for (int i = 0; i < 4; i++) {
        size_t base = (size_t)(m0 + tg * 4 + i) * N_COLS + c0 + cg * 5;
#pragma unroll
        for (int j = 0; j < 5; j++) g_S[base + j] = acc[i][j];
    }

    // ---- fused router (cols 40..79 blocks hold the 16 logits locally) ----
    if (blockIdx.x == 1) {
#pragma unroll
        for (int i = 0; i < 4; i++)
#pragma unroll
            for (int j = 0; j < 5; j++)
                xs[tg * 4 + i][cg * 5 + j] = acc[i][j];
        __syncthreads();

        if (tid < 128) {
            int t = m0 + tid;
            float p[N_EXP];
            float mx = -1e30f;
#pragma unroll
            for (int e = 0; e < N_EXP; e++) {
                p[e] = xs[tid][24 + e];   // local col 24+e == global col 64+e
                mx = fmaxf(mx, p[e]);
            }
            float sum = 0.f;
#pragma unroll
            for (int e = 0; e < N_EXP; e++) { p[e] = __expf(p[e] - mx); sum += p[e]; }
            float inv = 1.f / sum;
#pragma unroll
            for (int e = 0; e < N_EXP; e++) p[e] *= inv;

            int b1 = -1; float v1 = -1.f;
#pragma unroll
            for (int e = 0; e < N_EXP; e++)
                if (p[e] > v1) { v1 = p[e]; b1 = e; }
            int b2 = -1; float v2 = -1.f;
#pragma unroll
            for (int e = 0; e < N_EXP; e++)
                if (e != b1 && p[e] > v2) { v2 = p[e]; b2 = e; }

            float denom = 1.f / (v1 + v2 + 1e-6f);
            float w1v = v1 * denom, w2v = v2 * denom;
            int lo = min(b1, b2), hi = max(b1, b2);
            float wlo = (b1 < b2) ? w1v : w2v;
            float whi = (b1 < b2) ? w2v : w1v;
            int bin = lo * N_EXP + hi;
            int slot = atomicAdd(&g_pcnt[bin], 1);
            if (slot < PAIR_CAP) {
                g_ptok[bin * PAIR_CAP + slot] = t;
                g_pw [bin * PAIR_CAP + slot] = make_float2(wlo, whi);
            }
        }
    }
}

// ============================================================================
// Kernel 3: base GEMM via mma.sync fp16: out = xh @ wh^T + b  (STG epilogue)
// CTA tile 128x128, BK=32, 8 warps (2x4), warp tile 64x32, 3-stage cp.async.
// ============================================================================
#define BK       32
#define NCHUNK   (D_IN / BK)                 // 64
#define MAT_BYTES (128 * 80)                 // 10240
#define STAGE_BYTES (2 * MAT_BYTES)          // 20480 (Ah | Bh)
#define SMEM_DYN (3 * STAGE_BYTES)           // 61440

__global__ __launch_bounds__(256, 2) void k3_mma_gemm(
    const float* __restrict__ bias, float* __restrict__ out)
{
    extern __shared__ char sm[];
    const int tid  = threadIdx.x;
    const int wid  = tid >> 5;
    const int lane = tid & 31;
    const int g    = lane >> 2;
    const int t4   = lane & 3;

    const int m0 = blockIdx.y * 128;
    const int n0 = blockIdx.x * 128;
    const int wm = (wid >> 2) * 64;
    const int wn = (wid & 3) * 32;

    const uint32_t sbase = smem_u32(sm);

    const int a_row = ((lane >> 3) & 1) * 8 + (lane & 7);
    const int a_kb  = (lane >> 4) * 16;
    const int b_row = ((lane >> 4) & 1) * 8 + (lane & 7);
    const int b_kb  = ((lane >> 3) & 1) * 16;

    float acc[4][4][4];
#pragma unroll
    for (int mi = 0; mi < 4; mi++)
#pragma unroll
        for (int ni = 0; ni < 4; ni++)
#pragma unroll
            for (int r = 0; r < 4; r++) acc[mi][ni][r] = 0.f;

    auto load_chunk = [&](int c) {
        const int p  = c % 3;
        const int k0 = c * BK;
#pragma unroll
        for (int it = 0; it < 4; it++) {
            int q    = tid + it * 256;
            int mat  = q >> 9;
            int row  = (q >> 2) & 127;
            int quad = q & 3;
            const __half* src = mat ? g_wh : g_xh;
            int grow = (mat ? n0 : m0) + row;
            uint32_t saddr = sbase + p * STAGE_BYTES + mat * MAT_BYTES
                           + row * 80 + quad * 16;
            cp16(saddr, &src[(size_t)grow * D_IN + k0 + quad * 8]);
        }
        CP_COMMIT();
    };

    load_chunk(0);
    load_chunk(1);

    for (int c = 0; c < NCHUNK; c++) {
        if (c + 2 < NCHUNK) { load_chunk(c + 2); CP_WAIT(2); }
        else if (c + 1 < NCHUNK) { CP_WAIT(1); }
        else { CP_WAIT(0); }
        __syncthreads();

        const uint32_t stg = sbase + (c % 3) * STAGE_BYTES;
        const uint32_t sAh = stg;
        const uint32_t sBh = stg + MAT_BYTES;

#pragma unroll
        for (int ks = 0; ks < 2; ks++) {
            const uint32_t kso = ks * 32;

            uint32_t aH[4][4];
#pragma unroll
            for (int mi = 0; mi < 4; mi++) {
                uint32_t aoff = (uint32_t)((wm + mi * 16 + a_row) * 80) + kso + a_kb;
                ldmatrix_x4(aH[mi], sAh + aoff);
            }
            uint32_t bH[4][2];
#pragma unroll
            for (int nj = 0; nj < 2; nj++) {
                uint32_t boff = (uint32_t)((wn + nj * 16 + b_row) * 80) + kso + b_kb;
                uint32_t th[4];
                ldmatrix_x4(th, sBh + boff);
                bH[nj * 2][0] = th[0]; bH[nj * 2][1] = th[1];
                bH[nj * 2 + 1][0] = th[2]; bH[nj * 2 + 1][1] = th[3];
            }

#pragma unroll
            for (int ni = 0; ni < 4; ni++)
#pragma unroll
                for (int mi = 0; mi < 4; mi++)
                    mma16816h(acc[mi][ni], aH[mi], bH[ni][0], bH[ni][1]);
        }
        __syncthreads();
    }

#pragma unroll
    for (int mi = 0; mi < 4; mi++) {
        int row = m0 + wm + mi * 16 + g;
#pragma unroll
        for (int ni = 0; ni < 4; ni++) {
            int col = n0 + wn + ni * 8 + t4 * 2;
            float2 bv = *(const float2*)&bias[col];
            float2 o0, o1;
            o0.x = acc[mi][ni][0] + bv.x;
            o0.y = acc[mi][ni][1] + bv.y;
            o1.x = acc[mi][ni][2] + bv.x;
            o1.y = acc[mi][ni][3] + bv.y;
            *(float2*)&out[(size_t)row * D_OUT + col]       = o0;
            *(float2*)&out[(size_t)(row + 8) * D_OUT + col] = o1;
        }
    }
}

// ============================================================================
// Kernel 4: pair-delta via fp16 mma. Block = (pair bin, 64-slot tile).
// H2 (64 slots x 128 = [w_lo*h | w_hi*h]) fp16 in smem; B chunks
// (128 d x 128 = [B_lo | B_hi], 256B/row) double-buffered. 8 warps:
// sg(4 slot-groups x16) x dg(2 d-groups x64). ONE red row per token.
// ============================================================================
#define P_STR    272                          // 256B data + 16 pad
#define P_H      (64 * P_STR)                 // 17408
#define P_B      (128 * P_STR)                // 34816
#define P_SMEM   (P_H + 2 * P_B + 256)        // 87296

__global__ __launch_bounds__(256) void k4_pair(
    const __half* __restrict__ Bh, float* __restrict__ out)
{
    extern __shared__ char sm4[];
    const uint32_t sbase = smem_u32(sm4);
    const uint32_t sH = sbase;
    const uint32_t sB = sbase + P_H;
    int* stok = (int*)(sm4 + P_H + 2 * P_B);

    const int bin   = blockIdx.x >> 2;        // 256 bins
    const int stile = blockIdx.x & 3;         // 4 slot tiles of 64
    const int cnt   = min(g_pcnt[bin], PAIR_CAP);
    const int tid   = threadIdx.x;
    const int wid   = tid >> 5;
    const int lane  = tid & 31;
    const int g     = lane >> 2;
    const int t4    = lane & 3;
    const int sg    = wid & 3;                // slot group (16 slots)
    const int dg    = wid >> 2;               // d group (64 d)

    if (stile * 64 >= cnt) return;

    const int e_lo = bin >> 4;
    const int e_hi = bin & 15;
    const __half* Blo = Bh + (size_t)e_lo * D_OUT * R_RANK;
    const __half* Bhi = Bh + (size_t)e_hi * D_OUT * R_RANK;

    const int a_row = ((lane >> 3) & 1) * 8 + (lane & 7);
    const int a_kb  = (lane >> 4) * 16;
    const int b_row = ((lane >> 4) & 1) * 8 + (lane & 7);
    const int b_kb  = ((lane >> 3) & 1) * 16;

    for (int s0 = stile * 64; s0 < cnt; s0 += 4 * 64) {
        // ---- build H2 tile: 64 slots x 128 fp16 ([w_lo*h | w_hi*h]) ----
        {
            int slot = tid >> 2;               // 0..63
            int seg  = tid & 3;                // 4 segs x 32 halfs (64B)
            int s    = s0 + slot;
            int t = -1; float wlo = 0.f, whi = 0.f;
            if (s < cnt) {
                t = g_ptok[bin * PAIR_CAP + s];
                float2 ww = g_pw[bin * PAIR_CAP + s];
                wlo = ww.x; whi = ww.y;
            }
            float w  = (seg < 2) ? wlo : whi;
            int   hb = (seg & 1) * 32;         // h index base
            float vv[32];
#pragma unroll
            for (int j = 0; j < 32; j++) vv[j] = 0.f;
            if (t >= 0) {
                const float4* hp = (const float4*)&g_S[(size_t)t * N_COLS + hb];
#pragma unroll
                for (int j = 0; j < 8; j++) *(float4*)&vv[j * 4] = hp[j];
            }
            __half hh[32];
#pragma unroll
            for (int j = 0; j < 32; j++) hh[j] = __float2half_rn(vv[j] * w);
            char* hp = sm4 + slot * P_STR + seg * 64;
#pragma unroll
            for (int j = 0; j < 4; j++)
                *(uint4*)(hp + j * 16) = *(uint4*)&hh[j * 8];
            if (seg == 0) stok[slot] = t;
        }

        // ---- B chunk pipeline (16 chunks of 128 d); 256B per d row ----
        auto loadB = [&](int i) {
            uint32_t dst = sB + (i & 1) * P_B;
            int d0 = i * 128;
#pragma unroll
            for (int it = 0; it < 8; it++) {
                int q   = tid + it * 256;      // 0..2047
                int row = q >> 4;              // 0..127
                int qd  = q & 15;              // 16 quads: 0-7 B_lo, 8-15 B_hi
                const __half* src = (qd < 8) ? Blo : Bhi;
                cp16(dst + row * P_STR + qd * 16,
                     (const char*)&src[(size_t)(d0 + row) * R_RANK] + (qd & 7) * 16);
            }
            CP_COMMIT();
        };

        loadB(0);
        __syncthreads();   // H2 + stok visible

        for (int i = 0; i < 16; i++) {
            if (i + 1 < 16) { loadB(i + 1); CP_WAIT(1); }
            else { CP_WAIT(0); }
            __syncthreads();

            const uint32_t stg = sB + (i & 1) * P_B;

            float acc[8][4];
#pragma unroll
            for (int ni = 0; ni < 8; ni++)
#pragma unroll
                for (int r = 0; r < 4; r++) acc[ni][r] = 0.f;

#pragma unroll
            for (int ks = 0; ks < 8; ks++) {
                uint32_t a[4];
                ldmatrix_x4(a, sH + (uint32_t)((sg * 16 + a_row) * P_STR) + ks * 32 + a_kb);
#pragma unroll
                for (int nj = 0; nj < 4; nj++) {
                    uint32_t bf[4];
                    ldmatrix_x4(bf, stg + (uint32_t)((dg * 64 + nj * 16 + b_row) * P_STR)
                                     + ks * 32 + b_kb);
                    mma16816h(acc[nj * 2],     a, bf[0], bf[1]);
                    mma16816h(acc[nj * 2 + 1], a, bf[2], bf[3]);
                }
            }

            // ---- epilogue: single red row per token ----
            int t0 = stok[sg * 16 + g];
            int t1 = stok[sg * 16 + g + 8];
            int d0 = i * 128;
#pragma unroll
            for (int ni = 0; ni < 8; ni++) {
                int col = d0 + dg * 64 + ni * 8 + t4 * 2;
                if (t0 >= 0) red_v2(&out[(size_t)t0 * D_OUT + col], acc[ni][0], acc[ni][1]);
                if (t1 >= 0) red_v2(&out[(size_t)t1 * D_OUT + col], acc[ni][2], acc[ni][3]);
            }
            __syncthreads();
        }
    }
}

// ============================================================================
// launch — side: k0(x) -> ev_x -> k1(+router) -> k0(B) -> ev_join
//          main: k0(W), wait ev_x, k3 (STG), wait ev_join, k4_pair.
// ============================================================================
extern "C" void kernel_launch(void* const* d_in, const int* in_sizes, int n_in,
                              void* d_out, int out_size)
{
    const float* x   = (const float*)d_in[0];
    const float* Wb  = (const float*)d_in[1];
    const float* bb  = (const float*)d_in[2];
    const float* A   = (const float*)d_in[3];
    const float* Bm  = (const float*)d_in[4];
    const float* Wr  = (const float*)d_in[5];
    float* out       = (float*)d_out;

    (void)in_sizes; (void)n_in; (void)out_size;

    __half *p_xh, *p_wh, *p_bh;
    int* p_pcnt;
    cudaGetSymbolAddress((void**)&p_xh, g_xh);
    cudaGetSymbolAddress((void**)&p_wh, g_wh);
    cudaGetSymbolAddress((void**)&p_bh, g_bh);
    cudaGetSymbolAddress((void**)&p_pcnt, g_pcnt);

    static cudaStream_t s1 = nullptr;
    static cudaEvent_t  ev_fork = nullptr, ev_x = nullptr, ev_join = nullptr;
    static bool inited = false;
    if (!inited) {
        cudaStreamCreateWithFlags(&s1, cudaStreamNonBlocking);
        cudaEventCreateWithFlags(&ev_fork, cudaEventDisableTiming);
        cudaEventCreateWithFlags(&ev_x,    cudaEventDisableTiming);
        cudaEventCreateWithFlags(&ev_join, cudaEventDisableTiming);
        cudaFuncSetAttribute(k3_mma_gemm, cudaFuncAttributeMaxDynamicSharedMemorySize, SMEM_DYN);
        cudaFuncSetAttribute(k4_pair,     cudaFuncAttributeMaxDynamicSharedMemorySize, P_SMEM);
        inited = true;
    }

    int n4x = T_TOK * D_IN / 4, n4w = D_OUT * D_IN / 4;
    int n4b = N_EXP * D_OUT * R_RANK / 4;

    // zero pair counters, then fork
    cudaMemsetAsync(p_pcnt, 0, N_PAIR * sizeof(int), 0);
    cudaEventRecord(ev_fork, 0);
    cudaStreamWaitEvent(s1, ev_fork, 0);

    // side chain: x convert (k3 dependency) -> small GEMM + router -> B convert
    k0_cvt<<<(n4x + 255) / 256, 256, 0, s1>>>(x, p_xh, n4x);
    cudaEventRecord(ev_x, s1);
    k1_small_gemm<<<dim3(2, T_TOK / 128), 256, 0, s1>>>(x, A, Wr);
    k0_cvt<<<(n4b + 255) / 256, 256, 0, s1>>>(Bm, p_bh, n4b);
    cudaEventRecord(ev_join, s1);

    // main chain: W convert (concurrent with x convert), then big GEMM
    k0_cvt<<<(n4w + 255) / 256, 256>>>(Wb, p_wh, n4w);
    cudaStreamWaitEvent(0, ev_x, 0);
    k3_mma_gemm<<<dim3(D_OUT / 128, T_TOK / 128), 256, SMEM_DYN>>>(bb, out);

    // join, then pair-delta accumulate
    cudaStreamWaitEvent(0, ev_join, 0);
    k4_pair<<<N_PAIR * 4, 256, P_SMEM>>>(p_bh, out);
}

// round 17
// speedup vs baseline: 1.0143x; 1.0143x over previous
#include <cuda_runtime.h>
#include <cuda_fp16.h>
#include <cstdint>

// Problem constants (fixed by setup_inputs)
#define T_TOK   8192      // B*S = 4*2048
#define D_IN    2048
#define D_OUT   2048
#define R_RANK  64
#define N_EXP   16
#define N_COLS  80        // R + E combined small-GEMM width
#define N_PAIR  256       // expert-pair bins (lo*16+hi, lo<hi populated)

// ---------------- device scratch (no allocations allowed) ----------------
__device__ float  g_S[T_TOK * N_COLS];        // [token][0..63]=res_hidden, [64..79]=router logits
__device__ int    g_pcnt[N_PAIR];             // per-pair token counts
__device__ int    g_ptok[N_PAIR * T_TOK / 4]; // pair token ids (cap 2048/bin)
__device__ float2 g_pw [N_PAIR * T_TOK / 4];  // (w_lo, w_hi) per slot
// fp16 copies for the tensor-core GEMMs
__device__ __half g_xh[T_TOK * D_IN];
__device__ __half g_wh[D_OUT * D_IN];
__device__ __half g_bh[N_EXP * D_OUT * R_RANK];

#define PAIR_CAP (T_TOK / 4)   // 2048 slots per bin

// ---------------- helpers ----------------
__device__ __forceinline__ uint32_t smem_u32(const void* p) {
    uint32_t a;
    asm("{ .reg .u64 t; cvta.to.shared.u64 t, %1; cvt.u32.u64 %0, t; }" : "=r"(a) : "l"(p));
    return a;
}
__device__ __forceinline__ void cp16(uint32_t s, const void* g) {
    asm volatile("cp.async.cg.shared.global [%0], [%1], 16;" :: "r"(s), "l"(g) : "memory");
}
__device__ __forceinline__ void ldmatrix_x4(uint32_t* r, uint32_t addr) {
    asm volatile("ldmatrix.sync.aligned.m8n8.x4.shared.b16 {%0,%1,%2,%3}, [%4];"
                 : "=r"(r[0]), "=r"(r[1]), "=r"(r[2]), "=r"(r[3]) : "r"(addr));
}
__device__ __forceinline__ void mma16816h(float* c, const uint32_t* a, uint32_t b0, uint32_t b1) {
    asm volatile(
        "mma.sync.aligned.m16n8k16.row.col.f32.f16.f16.f32 "
        "{%0,%1,%2,%3}, {%4,%5,%6,%7}, {%8,%9}, {%0,%1,%2,%3};"
        : "+f"(c[0]), "+f"(c[1]), "+f"(c[2]), "+f"(c[3])
        : "r"(a[0]), "r"(a[1]), "r"(a[2]), "r"(a[3]), "r"(b0), "r"(b1));
}
__device__ __forceinline__ void red_v2(float* p, float x, float y) {
    asm volatile("red.global.add.v2.f32 [%0], {%1,%2};"
                 :: "l"(p), "f"(x), "f"(y) : "memory");
}
#define CP_COMMIT() asm volatile("cp.async.commit_group;" ::: "memory")
#define CP_WAIT(n)  asm volatile("cp.async.wait_group %0;" :: "n"(n) : "memory")

// ============================================================================
// Kernel 0: fp32 -> fp16 (single-tensor form, used for B on the side stream)
// ============================================================================
__global__ __launch_bounds__(256) void k0_cvt(
    const float* __restrict__ src, __half* __restrict__ dst, int n4)
{
    int i = blockIdx.x * blockDim.x + threadIdx.x;
    if (i >= n4) return;
    float4 v = *(const float4*)&src[(size_t)i * 4];
    __half h[4];
    h[0] = __float2half_rn(v.x); h[1] = __float2half_rn(v.y);
    h[2] = __float2half_rn(v.z); h[3] = __float2half_rn(v.w);
    *(uint2*)&dst[(size_t)i * 4] = *(uint2*)h;
}

// Dual-tensor convert: blocks [0, bx) -> (s1,d1), rest -> (s2,d2).
// Uniform per-block branch; inner code identical to k0_cvt.
__global__ __launch_bounds__(256) void k0_cvt_dual(
    const float* __restrict__ s1, __half* __restrict__ d1, int bx,
    const float* __restrict__ s2, __half* __restrict__ d2)
{
    const float* src; __half* dst; int i;
    if (blockIdx.x < (unsigned)bx) { src = s1; dst = d1; i = blockIdx.x * 256 + threadIdx.x; }
    else { src = s2; dst = d2; i = (blockIdx.x - bx) * 256 + threadIdx.x; }
    float4 v = *(const float4*)&src[(size_t)i * 4];
    __half h[4];
    h[0] = __float2half_rn(v.x); h[1] = __float2half_rn(v.y);
    h[2] = __float2half_rn(v.z); h[3] = __float2half_rn(v.w);
    *(uint2*)&dst[(size_t)i * 4] = *(uint2*)h;
}

// ============================================================================
// Kernel 1: S = x @ [A^T | W_router^T]  (fp32 SIMT) + fused top-2 pair router
// ============================================================================
__global__ __launch_bounds__(256) void k1_small_gemm(
    const float* __restrict__ x,
    const float* __restrict__ A,
    const float* __restrict__ Wr)
{
    __shared__ float xs[128][68];
    __shared__ float ws[40][68];

    const int tid = threadIdx.x;
    const int m0 = blockIdx.y * 128;
    const int c0 = blockIdx.x * 40;
    const int tg = tid >> 3;
    const int cg = tid & 7;

    float acc[4][5];
#pragma unroll
    for (int i = 0; i < 4; i++)
#pragma unroll
        for (int j = 0; j < 5; j++) acc[i][j] = 0.f;

    for (int k0 = 0; k0 < D_IN; k0 += 64) {
#pragma unroll
        for (int it = 0; it < 8; it++) {
            int q = tid + it * 256;
            int row = q >> 4;
            int kc = (q & 15) << 2;
            float4 v = *(const float4*)&x[(size_t)(m0 + row) * D_IN + k0 + kc];
            *(float4*)&xs[row][kc] = v;
        }
        for (int q = tid; q < 40 * 16; q += 256) {
            int col = q >> 4;
            int kc = (q & 15) << 2;
            int gc = c0 + col;
            const float* src = (gc < R_RANK) ? (A + (size_t)gc * D_IN)
                                             : (Wr + (size_t)(gc - R_RANK) * D_IN);
            float4 v = *(const float4*)&src[k0 + kc];
            *(float4*)&ws[col][kc] = v;
        }
        __syncthreads();

#pragma unroll 16
        for (int kk = 0; kk < 64; kk++) {
            float av[4], bv[5];
#pragma unroll
            for (int i = 0; i < 4; i++) av[i] = xs[tg * 4 + i][kk];
#pragma unroll
            for (int j = 0; j < 5; j++) bv[j] = ws[cg * 5 + j][kk];
#pragma unroll
            for (int i = 0; i < 4; i++)
#pragma unroll
                for (int j = 0; j < 5; j++) acc[i][j] += av[i] * bv[j];
        }
        __syncthreads();
    }

#pragma unroll
    for (int i = 0; i < 4; i++) {
        size_t base = (size_t)(m0 + tg * 4 + i) * N_COLS + c0 + cg * 5;
#pragma unroll
        for (int j = 0; j < 5; j++) g_S[base + j] = acc[i][j];
    }

    // ---- fused router (cols 40..79 blocks hold the 16 logits locally) ----
    if (blockIdx.x == 1) {
#pragma unroll
        for (int i = 0; i < 4; i++)
#pragma unroll
            for (int j = 0; j < 5; j++)
                xs[tg * 4 + i][cg * 5 + j] = acc[i][j];
        __syncthreads();

        if (tid < 128) {
            int t = m0 + tid;
            float p[N_EXP];
            float mx = -1e30f;
#pragma unroll
            for (int e = 0; e < N_EXP; e++) {
                p[e] = xs[tid][24 + e];   // local col 24+e == global col 64+e
                mx = fmaxf(mx, p[e]);
            }
            float sum = 0.f;
#pragma unroll
            for (int e = 0; e < N_EXP; e++) { p[e] = __expf(p[e] - mx); sum += p[e]; }
            float inv = 1.f / sum;
#pragma unroll
            for (int e = 0; e < N_EXP; e++) p[e] *= inv;

            int b1 = -1; float v1 = -1.f;
#pragma unroll
            for (int e = 0; e < N_EXP; e++)
                if (p[e] > v1) { v1 = p[e]; b1 = e; }
            int b2 = -1; float v2 = -1.f;
#pragma unroll
            for (int e = 0; e < N_EXP; e++)
                if (e != b1 && p[e] > v2) { v2 = p[e]; b2 = e; }

            float denom = 1.f / (v1 + v2 + 1e-6f);
            float w1v = v1 * denom, w2v = v2 * denom;
            int lo = min(b1, b2), hi = max(b1, b2);
            float wlo = (b1 < b2) ? w1v : w2v;
            float whi = (b1 < b2) ? w2v : w1v;
            int bin = lo * N_EXP + hi;
            int slot = atomicAdd(&g_pcnt[bin], 1);
            if (slot < PAIR_CAP) {
                g_ptok[bin * PAIR_CAP + slot] = t;
                g_pw [bin * PAIR_CAP + slot] = make_float2(wlo, whi);
            }
        }
    }
}

// ============================================================================
// Kernel 3: base GEMM via mma.sync fp16: out = xh @ wh^T + b  (STG epilogue)
// CTA tile 128x128, BK=32, 8 warps (2x4), warp tile 64x32, 3-stage cp.async.
// ============================================================================
#define BK       32
#define NCHUNK   (D_IN / BK)                 // 64
#define MAT_BYTES (128 * 80)                 // 10240
#define STAGE_BYTES (2 * MAT_BYTES)          // 20480 (Ah | Bh)
#define SMEM_DYN (3 * STAGE_BYTES)           // 61440

__global__ __launch_bounds__(256, 2) void k3_mma_gemm(
    const float* __restrict__ bias, float* __restrict__ out)
{
    extern __shared__ char sm[];
    const int tid  = threadIdx.x;
    const int wid  = tid >> 5;
    const int lane = tid & 31;
    const int g    = lane >> 2;
    const int t4   = lane & 3;

    const int m0 = blockIdx.y * 128;
    const int n0 = blockIdx.x * 128;
    const int wm = (wid >> 2) * 64;
    const int wn = (wid & 3) * 32;

    const uint32_t sbase = smem_u32(sm);

    const int a_row = ((lane >> 3) & 1) * 8 + (lane & 7);
    const int a_kb  = (lane >> 4) * 16;
    const int b_row = ((lane >> 4) & 1) * 8 + (lane & 7);
    const int b_kb  = ((lane >> 3) & 1) * 16;

    float acc[4][4][4];
#pragma unroll
    for (int mi = 0; mi < 4; mi++)
#pragma unroll
        for (int ni = 0; ni < 4; ni++)
#pragma unroll
            for (int r = 0; r < 4; r++) acc[mi][ni][r] = 0.f;

    auto load_chunk = [&](int c) {
        const int p  = c % 3;
        const int k0 = c * BK;
#pragma unroll
        for (int it = 0; it < 4; it++) {
            int q    = tid + it * 256;
            int mat  = q >> 9;
            int row  = (q >> 2) & 127;
            int quad = q & 3;
            const __half* src = mat ? g_wh : g_xh;
            int grow = (mat ? n0 : m0) + row;
            uint32_t saddr = sbase + p * STAGE_BYTES + mat * MAT_BYTES
                           + row * 80 + quad * 16;
            cp16(saddr, &src[(size_t)grow * D_IN + k0 + quad * 8]);
        }
        CP_COMMIT();
    };

    load_chunk(0);
    load_chunk(1);

    for (int c = 0; c < NCHUNK; c++) {
        if (c + 2 < NCHUNK) { load_chunk(c + 2); CP_WAIT(2); }
        else if (c + 1 < NCHUNK) { CP_WAIT(1); }
        else { CP_WAIT(0); }
        __syncthreads();

        const uint32_t stg = sbase + (c % 3) * STAGE_BYTES;
        const uint32_t sAh = stg;
        const uint32_t sBh = stg + MAT_BYTES;

#pragma unroll
        for (int ks = 0; ks < 2; ks++) {
            const uint32_t kso = ks * 32;

            uint32_t aH[4][4];
#pragma unroll
            for (int mi = 0; mi < 4; mi++) {
                uint32_t aoff = (uint32_t)((wm + mi * 16 + a_row) * 80) + kso + a_kb;
                ldmatrix_x4(aH[mi], sAh + aoff);
            }
            uint32_t bH[4][2];
#pragma unroll
            for (int nj = 0; nj < 2; nj++) {
                uint32_t boff = (uint32_t)((wn + nj * 16 + b_row) * 80) + kso + b_kb;
                uint32_t th[4];
                ldmatrix_x4(th, sBh + boff);
                bH[nj * 2][0] = th[0]; bH[nj * 2][1] = th[1];
                bH[nj * 2 + 1][0] = th[2]; bH[nj * 2 + 1][1] = th[3];
            }

#pragma unroll
            for (int ni = 0; ni < 4; ni++)
#pragma unroll
                for (int mi = 0; mi < 4; mi++)
                    mma16816h(acc[mi][ni], aH[mi], bH[ni][0], bH[ni][1]);
        }
        __syncthreads();
    }

#pragma unroll
    for (int mi = 0; mi < 4; mi++) {
        int row = m0 + wm + mi * 16 + g;
#pragma unroll
        for (int ni = 0; ni < 4; ni++) {
            int col = n0 + wn + ni * 8 + t4 * 2;
            float2 bv = *(const float2*)&bias[col];
            float2 o0, o1;
            o0.x = acc[mi][ni][0] + bv.x;
            o0.y = acc[mi][ni][1] + bv.y;
            o1.x = acc[mi][ni][2] + bv.x;
            o1.y = acc[mi][ni][3] + bv.y;
            *(float2*)&out[(size_t)row * D_OUT + col]       = o0;
            *(float2*)&out[(size_t)(row + 8) * D_OUT + col] = o1;
        }
    }
}

// ============================================================================
// Kernel 4: pair-delta via fp16 mma. Block = (pair bin, 32-slot tile).
// H2 (32 slots x 128 = [w_lo*h | w_hi*h]) fp16 in smem; B chunks
// (128 d x 128 = [B_lo | B_hi], 256B/row) double-buffered cp.async. 8 warps:
// sg(2 slot-groups x16) x dg(4 d-groups x32). ONE red row per token.
// ============================================================================
#define P_STR    272                          // 256B data + 16 pad
#define P_H      (32 * P_STR)                 // 8704
#define P_B      (128 * P_STR)                // 34816
#define P_SMEM   (P_H + 2 * P_B + 128)        // 78592

__global__ __launch_bounds__(256) void k4_pair(
    const __half* __restrict__ Bh, float* __restrict__ out)
{
    extern __shared__ char sm4[];
    const uint32_t sbase = smem_u32(sm4);
    const uint32_t sH = sbase;
    const uint32_t sB = sbase + P_H;
    int* stok = (int*)(sm4 + P_H + 2 * P_B);

    const int bin   = blockIdx.x >> 3;        // 256 bins
    const int stile = blockIdx.x & 7;         // 8 slot tiles of 32
    const int cnt   = min(g_pcnt[bin], PAIR_CAP);
    const int tid   = threadIdx.x;
    const int wid   = tid >> 5;
    const int lane  = tid & 31;
    const int g     = lane >> 2;
    const int t4    = lane & 3;
    const int sg    = wid & 1;                // slot group (16 slots)
    const int dg    = wid >> 1;               // d group (32 d)

    if (stile * 32 >= cnt) return;

    const int e_lo = bin >> 4;
    const int e_hi = bin & 15;
    const __half* Blo = Bh + (size_t)e_lo * D_OUT * R_RANK;
    const __half* Bhi = Bh + (size_t)e_hi * D_OUT * R_RANK;

    const int a_row = ((lane >> 3) & 1) * 8 + (lane & 7);
    const int a_kb  = (lane >> 4) * 16;
    const int b_row = ((lane >> 4) & 1) * 8 + (lane & 7);
    const int b_kb  = ((lane >> 3) & 1) * 16;

    for (int s0 = stile * 32; s0 < cnt; s0 += 8 * 32) {
        // ---- build H2 tile: 32 slots x 128 fp16 ([w_lo*h | w_hi*h]) ----
        if (tid < 128) {
            int slot = tid >> 2;
            int seg  = tid & 3;                // 4 segs x 32 halfs (64B)
            int s    = s0 + slot;
            int t = -1; float wlo = 0.f, whi = 0.f;
            if (s < cnt) {
                t = g_ptok[bin * PAIR_CAP + s];
                float2 ww = g_pw[bin * PAIR_CAP + s];
                wlo = ww.x; whi = ww.y;
            }
            float w  = (seg < 2) ? wlo : whi;
            int   hb = (seg & 1) * 32;         // h index base
            float vv[32];
#pragma unroll
            for (int j = 0; j < 32; j++) vv[j] = 0.f;
            if (t >= 0) {
                const float4* hp = (const float4*)&g_S[(size_t)t * N_COLS + hb];
#pragma unroll
                for (int j = 0; j < 8; j++) *(float4*)&vv[j * 4] = hp[j];
            }
            __half hh[32];
#pragma unroll
            for (int j = 0; j < 32; j++) hh[j] = __float2half_rn(vv[j] * w);
            char* hp = sm4 + slot * P_STR + seg * 64;
#pragma unroll
            for (int j = 0; j < 4; j++)
                *(uint4*)(hp + j * 16) = *(uint4*)&hh[j * 8];
            if (seg == 0) stok[slot] = t;
        }

        // ---- B chunk pipeline (16 chunks of 128 d); 256B per d row ----
        auto loadB = [&](int i) {
            uint32_t dst = sB + (i & 1) * P_B;
            int d0 = i * 128;
#pragma unroll
            for (int it = 0; it < 8; it++) {
                int q   = tid + it * 256;      // 0..2047
                int row = q >> 4;              // 0..127
                int qd  = q & 15;              // 16 quads: 0-7 B_lo, 8-15 B_hi
                const __half* src = (qd < 8) ? Blo : Bhi;
                cp16(dst + row * P_STR + qd * 16,
                     (const char*)&src[(size_t)(d0 + row) * R_RANK] + (qd & 7) * 16);
            }
            CP_COMMIT();
        };

        loadB(0);
        __syncthreads();   // H2 + stok visible

        for (int i = 0; i < 16; i++) {
            if (i + 1 < 16) { loadB(i + 1); CP_WAIT(1); }
            else { CP_WAIT(0); }
            __syncthreads();

            const uint32_t stg = sB + (i & 1) * P_B;

            float acc[4][4];
#pragma unroll
            for (int ni = 0; ni < 4; ni++)
#pragma unroll
                for (int r = 0; r < 4; r++) acc[ni][r] = 0.f;

#pragma unroll
            for (int ks = 0; ks < 8; ks++) {
                uint32_t a[4];
                ldmatrix_x4(a, sH + (uint32_t)((sg * 16 + a_row) * P_STR) + ks * 32 + a_kb);
#pragma unroll
                for (int nj = 0; nj < 2; nj++) {
                    uint32_t bf[4];
                    ldmatrix_x4(bf, stg + (uint32_t)((dg * 32 + nj * 16 + b_row) * P_STR)
                                     + ks * 32 + b_kb);
                    mma16816h(acc[nj * 2],     a, bf[0], bf[1]);
                    mma16816h(acc[nj * 2 + 1], a, bf[2], bf[3]);
                }
            }

            // ---- epilogue: single red row per token ----
            int t0 = stok[sg * 16 + g];
            int t1 = stok[sg * 16 + g + 8];
            int d0 = i * 128;
#pragma unroll
            for (int ni = 0; ni < 4; ni++) {
                int col = d0 + dg * 32 + ni * 8 + t4 * 2;
                if (t0 >= 0) red_v2(&out[(size_t)t0 * D_OUT + col], acc[ni][0], acc[ni][1]);
                if (t1 >= 0) red_v2(&out[(size_t)t1 * D_OUT + col], acc[ni][2], acc[ni][3]);
            }
            __syncthreads();
        }
    }
}

// ============================================================================
// launch — side: k1(+pair router) -> B convert; main: dual convert + k3 (STG).
// Join, then k4_pair red-accumulates delta.
// ============================================================================
extern "C" void kernel_launch(void* const* d_in, const int* in_sizes, int n_in,
                              void* d_out, int out_size)
{
    const float* x   = (const float*)d_in[0];
    const float* Wb  = (const float*)d_in[1];
    const float* bb  = (const float*)d_in[2];
    const float* A   = (const float*)d_in[3];
    const float* Bm  = (const float*)d_in[4];
    const float* Wr  = (const float*)d_in[5];
    float* out       = (float*)d_out;

    (void)in_sizes; (void)n_in; (void)out_size;

    __half *p_xh, *p_wh, *p_bh;
    int* p_pcnt;
    cudaGetSymbolAddress((void**)&p_xh, g_xh);
    cudaGetSymbolAddress((void**)&p_wh, g_wh);
    cudaGetSymbolAddress((void**)&p_bh, g_bh);
    cudaGetSymbolAddress((void**)&p_pcnt, g_pcnt);

    static cudaStream_t s1 = nullptr;
    static cudaEvent_t  ev_fork = nullptr, ev_join = nullptr;
    static bool inited = false;
    if (!inited) {
        cudaStreamCreateWithFlags(&s1, cudaStreamNonBlocking);
        cudaEventCreateWithFlags(&ev_fork, cudaEventDisableTiming);
        cudaEventCreateWithFlags(&ev_join, cudaEventDisableTiming);
        cudaFuncSetAttribute(k3_mma_gemm, cudaFuncAttributeMaxDynamicSharedMemorySize, SMEM_DYN);
        cudaFuncSetAttribute(k4_pair,     cudaFuncAttributeMaxDynamicSharedMemorySize, P_SMEM);
        inited = true;
    }

    int n4x = T_TOK * D_IN / 4, n4w = D_OUT * D_IN / 4;
    int n4b = N_EXP * D_OUT * R_RANK / 4;
    int bx  = n4x / 256;                       // x blocks in dual convert

    // zero pair counters, then fork
    cudaMemsetAsync(p_pcnt, 0, N_PAIR * sizeof(int), 0);
    cudaEventRecord(ev_fork, 0);
    cudaStreamWaitEvent(s1, ev_fork, 0);

    // side chain: small GEMM + fused pair router -> B convert
    k1_small_gemm<<<dim3(2, T_TOK / 128), 256, 0, s1>>>(x, A, Wr);
    k0_cvt       <<<(n4b + 255) / 256, 256, 0, s1>>>(Bm, p_bh, n4b);
    cudaEventRecord(ev_join, s1);

    // main chain: fused x+W convert (single launch) + big GEMM
    k0_cvt_dual<<<bx + n4w / 256, 256>>>(x, p_xh, bx, Wb, p_wh);
    k3_mma_gemm<<<dim3(D_OUT / 128, T_TOK / 128), 256, SMEM_DYN>>>(bb, out);

    // join, then pair-delta accumulate
    cudaStreamWaitEvent(0, ev_join, 0);
    k4_pair<<<N_PAIR * 8, 256, P_SMEM>>>(p_bh, out);
}